// round 12
// baseline (speedup 1.0000x reference)
#include <cuda_runtime.h>
#include <math.h>

#define FULLMASK 0xffffffffu
#define TWO_PI_F 6.2831853071795864f

// ---------------- sim14 single-layer op schedule (32 ops) ----------------
__constant__ int c_OPC[32] = {
    -1,-1,-1,-1,-1,-1,-1,-1,
     7, 6, 5, 4, 3, 2, 1, 0,
    -1,-1,-1,-1,-1,-1,-1,-1,
     7, 0, 1, 2, 3, 4, 5, 6};
__constant__ int c_OPT[32] = {
     0, 1, 2, 3, 4, 5, 6, 7,
     0, 7, 6, 5, 4, 3, 2, 1,
     0, 1, 2, 3, 4, 5, 6, 7,
     6, 7, 0, 1, 2, 3, 4, 5};

// ---------------- helpers ----------------
__device__ __forceinline__ float g4(float4 v, int i) {
    return (i == 0) ? v.x : (i == 1) ? v.y : (i == 2) ? v.z : v.w;
}
__device__ __forceinline__ float4 splat4(float v) { return make_float4(v, v, v, v); }
__device__ __forceinline__ float silu_f(float x) { return x * (1.f / (1.f + expf(-x))); }

// State layout (4 warps per batch element, 128 threads):
//   flat index n (10 bits): bit9..bit5 = wires 0..4 (lane bits 4..0),
//   bit4 = wire5 (tid bit 6), bit3 = wire6 (tid bit 5),
//   bit2 = wire7 (reg M=4), bit1 = wire8/anc0 (M=2), bit0 = wire9/anc1 (M=1).
//   Each thread holds 8 float2 (r = bits 2..0). select index s = r & 3.
#define OIDX(n) ((n) ^ (((n) >> 5) & 31))

// RY on a lane-bit wire
__device__ __forceinline__ void ry_lane(float2 (&st)[8], int lmask, int lb, int lane,
                                        float4 c, float4 s) {
    float sg = ((lane >> lb) & 1) ? 1.f : -1.f;
    float4 sv = make_float4(g4(s,0)*sg, g4(s,1)*sg, g4(s,2)*sg, g4(s,3)*sg);
#pragma unroll
    for (int r = 0; r < 8; ++r) {
        float ox = __shfl_xor_sync(FULLMASK, st[r].x, lmask);
        float oy = __shfl_xor_sync(FULLMASK, st[r].y, lmask);
        float pc = g4(c, r & 3), ps = g4(sv, r & 3);
        st[r].x = fmaf(pc, st[r].x, ps * ox);
        st[r].y = fmaf(pc, st[r].y, ps * oy);
    }
}

// RY on a reg-bit wire (mask M in {4,2,1})
template <int M>
__device__ __forceinline__ void ry_reg(float2 (&st)[8], float4 c, float4 s) {
#pragma unroll
    for (int r = 0; r < 8; ++r) {
        if ((r & M) == 0) {
            const int r1 = r | M;
            float pc = g4(c, r & 3), ps = g4(s, r & 3);
            float ax = st[r].x, ay = st[r].y, bx = st[r1].x, by = st[r1].y;
            st[r].x = fmaf(pc, ax, -ps * bx);
            st[r].y = fmaf(pc, ay, -ps * by);
            st[r1].x = fmaf(ps, ax, pc * bx);
            st[r1].y = fmaf(ps, ay, pc * by);
        }
    }
}

// CRX with target on a lane-bit wire. act = actBase && (crm==0 || (r&crm))
__device__ __forceinline__ void crx_lane(float2 (&st)[8], int tmask,
                                         bool actBase, int crm,
                                         float4 c, float4 s) {
#pragma unroll
    for (int r = 0; r < 8; ++r) {
        float ox = __shfl_xor_sync(FULLMASK, st[r].x, tmask);
        float oy = __shfl_xor_sync(FULLMASK, st[r].y, tmask);
        bool act = actBase && (crm == 0 || (r & crm) != 0);
        float pc = g4(c, r & 3), ps = g4(s, r & 3);
        float nx = fmaf(pc, st[r].x, ps * oy);
        float ny = fmaf(pc, st[r].y, -ps * ox);
        if (act) { st[r].x = nx; st[r].y = ny; }
    }
}

// CRX with target on a reg-bit wire (mask M)
template <int M>
__device__ __forceinline__ void crx_reg(float2 (&st)[8], bool actBase, int crm,
                                        float4 c, float4 s) {
#pragma unroll
    for (int r = 0; r < 8; ++r) {
        if ((r & M) == 0) {
            const int r1 = r | M;
            bool act = actBase && (crm == 0 || (r & crm) != 0);
            float pc = g4(c, r & 3), ps = g4(s, r & 3);
            float ax = st[r].x, ay = st[r].y, bx = st[r1].x, by = st[r1].y;
            float n0x = fmaf(pc, ax, ps * by);
            float n0y = fmaf(pc, ay, -ps * bx);
            float n1x = fmaf(pc, bx, ps * ay);
            float n1y = fmaf(pc, by, -ps * ax);
            if (act) { st[r] = make_float2(n0x, n0y); st[r1] = make_float2(n1x, n1y); }
        }
    }
}

// Op (RY or CRX) targeting a warp bit: smem exchange (float2). xm = 64 (w5) or 32 (w6)
__device__ __forceinline__ void warp_op(float2 (&st)[8], float2* sbuf,
                                        int tid, int xm, bool isRY,
                                        bool actBase, int crm, float4 c, float4 s) {
    __syncthreads();
#pragma unroll
    for (int r = 0; r < 8; ++r) sbuf[r * 128 + tid] = st[r];
    __syncthreads();
    const int p = tid ^ xm;
    const float sg = (tid & xm) ? 1.f : -1.f;
#pragma unroll
    for (int r = 0; r < 8; ++r) {
        float2 o = sbuf[r * 128 + p];
        float pc = g4(c, r & 3), ps = g4(s, r & 3);
        if (isRY) {
            float pss = sg * ps;
            st[r].x = fmaf(pc, st[r].x, pss * o.x);
            st[r].y = fmaf(pc, st[r].y, pss * o.y);
        } else {
            bool act = actBase && (crm == 0 || (r & crm) != 0);
            float nx = fmaf(pc, st[r].x, ps * o.y);
            float ny = fmaf(pc, st[r].y, -ps * o.x);
            if (act) { st[r].x = nx; st[r].y = ny; }
        }
    }
}

// RZ on a reg-bit wire (ancilla)
template <int M>
__device__ __forceinline__ void rz_reg(float2 (&st)[8], float c, float s) {
#pragma unroll
    for (int r = 0; r < 8; ++r) {
        float ss = (r & M) ? s : -s;
        float x = st[r].x, y = st[r].y;
        st[r].x = fmaf(c, x, -ss * y);
        st[r].y = fmaf(c, y, ss * x);
    }
}

__device__ __forceinline__ void cnot_st(float2 (&st)[8]) {
#pragma unroll
    for (int r = 0; r < 8; ++r) {
        if ((r & 3) == 2) { float2 tmp = st[r]; st[r] = st[r | 1]; st[r | 1] = tmp; }
    }
}

__device__ __forceinline__ void pcphase_g(float2 (&st)[8], float cphi, float sphi) {
#pragma unroll
    for (int r = 0; r < 8; ++r) {
        float ss = ((r & 3) == 0) ? sphi : -sphi;
        float x = st[r].x, y = st[r].y;
        st[r].x = fmaf(cphi, x, -ss * y);
        st[r].y = fmaf(cphi, y, ss * x);
    }
}

__device__ __forceinline__ void apply_op(float2 (&st)[8], int lane, int tid,
                                         float2* sbuf,
                                         int cw, int tw, float4 c, float4 s) {
    if (cw < 0) {  // RY
        if (tw < 5)       ry_lane(st, 1 << (4 - tw), 4 - tw, lane, c, s);
        else if (tw == 5) warp_op(st, sbuf, tid, 64, true, true, 0, c, s);
        else if (tw == 6) warp_op(st, sbuf, tid, 32, true, true, 0, c, s);
        else              ry_reg<4>(st, c, s);
    } else {       // CRX
        bool actBase; int crm = 0;
        if (cw < 5)       actBase = ((lane >> (4 - cw)) & 1) != 0;
        else if (cw == 5) actBase = ((tid >> 6) & 1) != 0;
        else if (cw == 6) actBase = ((tid >> 5) & 1) != 0;
        else { actBase = true; crm = 4; }
        if (tw < 5)       crx_lane(st, 1 << (4 - tw), actBase, crm, c, s);
        else if (tw == 5) warp_op(st, sbuf, tid, 64, false, actBase, crm, c, s);
        else if (tw == 6) warp_op(st, sbuf, tid, 32, false, actBase, crm, c, s);
        else              crx_reg<4>(st, actBase, crm, c, s);
    }
}

// sim14 with 2 layers (compact loop, runtime dispatch)
__device__ __forceinline__ void run_sim14_2l(float2 (&st)[8], int lane, int tid,
                                             float2* sbuf,
                                             const float4* tabc, const float4* tabs,
                                             bool adj) {
    if (!adj) {
#pragma unroll 1
        for (int step = 0; step < 64; ++step) {
            int o = step & 31;
            float4 c = tabc[step];
            float4 s = tabs[step];
            apply_op(st, lane, tid, sbuf, c_OPC[o], c_OPT[o], c, s);
        }
    } else {
#pragma unroll 1
        for (int step = 63; step >= 0; --step) {
            int o = step & 31;
            float4 c = tabc[step];
            float4 s0 = tabs[step];
            float4 s = make_float4(-s0.x, -s0.y, -s0.z, -s0.w);
            apply_op(st, lane, tid, sbuf, c_OPC[o], c_OPT[o], c, s);
        }
    }
}

__device__ __forceinline__ void do_prepare(float2 (&st)[8], const float2* tabp, bool adj) {
    if (!adj) {
#pragma unroll
        for (int ly = 0; ly < 2; ++ly) {
            float2 a  = tabp[ly*4+0]; ry_reg<2>(st, splat4(a.x),  splat4(a.y));
            float2 z  = tabp[ly*4+1]; rz_reg<2>(st, z.x, z.y);
            float2 a2 = tabp[ly*4+2]; ry_reg<1>(st, splat4(a2.x), splat4(a2.y));
            float2 z2 = tabp[ly*4+3]; rz_reg<1>(st, z2.x, z2.y);
            cnot_st(st);
        }
    } else {
#pragma unroll
        for (int ly = 1; ly >= 0; --ly) {
            cnot_st(st);
            float2 z2 = tabp[ly*4+3]; rz_reg<1>(st, z2.x, -z2.y);
            float2 a2 = tabp[ly*4+2]; ry_reg<1>(st, splat4(a2.x), splat4(-a2.y));
            float2 z  = tabp[ly*4+1]; rz_reg<2>(st, z.x, -z.y);
            float2 a  = tabp[ly*4+0]; ry_reg<2>(st, splat4(a.x),  splat4(-a.y));
        }
    }
}

// ---------------- fused kernel: MLP prologue + sim, 1 block = 1 batch row ----------------
__global__ void __launch_bounds__(128) k_all(
    const float* __restrict__ t, const float* __restrict__ z_t,
    const float* __restrict__ te_w1, const float* __restrict__ te_b1,
    const float* __restrict__ te_w2, const float* __restrict__ te_b2,
    const float* __restrict__ ip_w1, const float* __restrict__ ip_b1,
    const float* __restrict__ ip_w2, const float* __restrict__ ip_b2,
    const float* __restrict__ prep_p, const float* __restrict__ sig,
    const float* __restrict__ qff,
    const float* __restrict__ A_obs, const float* __restrict__ B_obs,
    const float* __restrict__ D_obs,
    const float* __restrict__ head_w, const float* __restrict__ head_b,
    float* __restrict__ out) {
    __shared__ float2 sbuf[1024];   // exchange / obs (8r x 128tid)
    __shared__ float4 tabc[64];
    __shared__ float4 tabs[64];
    __shared__ float2 tabq[32];
    __shared__ float2 tabp[8];
    __shared__ float2 tabsig[4];
    __shared__ float part[28];
    __shared__ float emb[128];
    __shared__ float hb[128];
    __shared__ float cat[256];
    __shared__ float g1[256];

    const int tid  = threadIdx.x;
    const int lane = tid & 31;
    const int warp = tid >> 5;
    const int b    = blockIdx.x;

    // ===== MLP prologue: compute ts for row b =====
    // stage A: sinusoidal embedding + copy z_t
    {
        float tv = t[b];
        int ii = tid & 63;
        float f = expf(-0.14391156831212787f * (float)ii);
        float a = tv * f;
        emb[tid] = (tid < 64) ? cosf(a) : sinf(a);
        cat[tid] = z_t[b * 128 + tid];
    }
    __syncthreads();

    // stage B: hb = silu(te_w1 @ emb + te_b1)
    {
        float acc = te_b1[tid];
        const float4* w4 = reinterpret_cast<const float4*>(te_w1 + tid * 128);
#pragma unroll 8
        for (int k4 = 0; k4 < 32; ++k4) {
            float4 wv = w4[k4];
            float4 x = *reinterpret_cast<const float4*>(&emb[k4 * 4]);
            acc = fmaf(wv.x, x.x, acc); acc = fmaf(wv.y, x.y, acc);
            acc = fmaf(wv.z, x.z, acc); acc = fmaf(wv.w, x.w, acc);
        }
        hb[tid] = silu_f(acc);
    }
    __syncthreads();

    // stage C: cat[128+j] = te_w2 @ hb + te_b2
    {
        float acc = te_b2[tid];
        const float4* w4 = reinterpret_cast<const float4*>(te_w2 + tid * 128);
#pragma unroll 8
        for (int k4 = 0; k4 < 32; ++k4) {
            float4 wv = w4[k4];
            float4 x = *reinterpret_cast<const float4*>(&hb[k4 * 4]);
            acc = fmaf(wv.x, x.x, acc); acc = fmaf(wv.y, x.y, acc);
            acc = fmaf(wv.z, x.z, acc); acc = fmaf(wv.w, x.w, acc);
        }
        cat[128 + tid] = acc;
    }
    __syncthreads();

    // stage D: g1 = silu(ip_w1 @ cat + ip_b1), 2 outputs/thread
    {
#pragma unroll
        for (int u = 0; u < 2; ++u) {
            int j = tid + u * 128;
            float acc = ip_b1[j];
            const float4* w4 = reinterpret_cast<const float4*>(ip_w1 + j * 256);
#pragma unroll 8
            for (int k4 = 0; k4 < 64; ++k4) {
                float4 wv = w4[k4];
                float4 x = *reinterpret_cast<const float4*>(&cat[k4 * 4]);
                acc = fmaf(wv.x, x.x, acc); acc = fmaf(wv.y, x.y, acc);
                acc = fmaf(wv.z, x.z, acc); acc = fmaf(wv.w, x.w, acc);
            }
            g1[j] = silu_f(acc);
        }
    }
    __syncthreads();

    // stage E: ts = sigmoid(ip_w2 @ g1 + ip_b2) * 2pi -> sincos tables directly
    {
        float* tabcf = reinterpret_cast<float*>(tabc);
        float* tabsf = reinterpret_cast<float*>(tabs);
#pragma unroll
        for (int u = 0; u < 2; ++u) {
            int j = tid + u * 128;     // j = s*64 + g
            float acc = ip_b2[j];
            const float4* w4 = reinterpret_cast<const float4*>(ip_w2 + j * 256);
#pragma unroll 8
            for (int k4 = 0; k4 < 64; ++k4) {
                float4 wv = w4[k4];
                float4 x = *reinterpret_cast<const float4*>(&g1[k4 * 4]);
                acc = fmaf(wv.x, x.x, acc); acc = fmaf(wv.y, x.y, acc);
                acc = fmaf(wv.z, x.z, acc); acc = fmaf(wv.w, x.w, acc);
            }
            float ang = TWO_PI_F / (1.f + expf(-acc));
            int s = j >> 6, g = j & 63;
            float sn, cc; sincosf(ang * 0.5f, &sn, &cc);
            tabcf[g * 4 + s] = cc;
            tabsf[g * 4 + s] = sn;
        }
    }
    // small tables
    if (tid < 32)      { float sn, cc; sincosf(qff[tid] * 0.5f, &sn, &cc); tabq[tid] = make_float2(cc, sn); }
    else if (tid < 40) { int q = tid - 32; float sn, cc; sincosf(prep_p[q] * 0.5f, &sn, &cc); tabp[q] = make_float2(cc, sn); }
    else if (tid < 44) { int q = tid - 40; float sn, cc; sincosf(sig[q], &sn, &cc); tabsig[q] = make_float2(cc, sn); }
    __syncthreads();

    // ===== state-vector simulation =====
    float2 st[8];
#pragma unroll
    for (int r = 0; r < 8; ++r) st[r] = make_float2(0.f, 0.f);
    if (tid == 0) st[0].x = 1.f;

    { float2 p = tabsig[0]; pcphase_g(st, p.x, p.y); }
#pragma unroll 1
    for (int k = 0; k < 3; ++k) {
        do_prepare(st, tabp, false);
        run_sim14_2l(st, lane, tid, sbuf, tabc, tabs, (k & 1) != 0);
        do_prepare(st, tabp, true);
        float2 p = tabsig[k + 1];
        pcphase_g(st, p.x, p.y);
    }
    // final sim14 with qff params, 1 layer (uniform theta)
#pragma unroll 1
    for (int step = 0; step < 32; ++step) {
        float2 tq = tabq[step];
        apply_op(st, lane, tid, sbuf, c_OPC[step], c_OPT[step],
                 splat4(tq.x), splat4(tq.y));
    }

    // dump state to shared (swizzled) for expectation values
    __syncthreads();
#pragma unroll
    for (int r = 0; r < 8; ++r) {
        int n = (lane << 5) | (warp << 3) | r;
        sbuf[OIDX(n)] = st[r];
    }
    __syncthreads();

#pragma unroll 1
    for (int w = 0; w < 7; ++w) {
        const float* Aw = A_obs + w * 6;
        const float* Bw = B_obs + w * 6;
        const float* Dw = D_obs + w * 4;
        float d0 = 2.f * Dw[1], d1 = 2.f * Dw[2], d2 = 2.f * Dw[3];
        float a10 = Aw[0], b10 = Bw[0], a20 = Aw[1], b20 = Bw[1], a21 = Aw[2], b21 = Bw[2];
        float a30 = Aw[3], b30 = Bw[3], a31 = Aw[4], b31 = Bw[4], a32 = Aw[5], b32 = Bw[5];
        int b1 = 8 - w;
        int m1 = 1 << b1, m0 = m1 << 1;
        int lowmask = m1 - 1;
        float acc = 0.f;
#pragma unroll
        for (int it = 0; it < 2; ++it) {
            int gi = tid + it * 128;
            int n = ((gi & ~lowmask) << 2) | (gi & lowmask);
            float2 v0 = sbuf[OIDX(n)];
            float2 v1 = sbuf[OIDX(n + m1)];
            float2 v2 = sbuf[OIDX(n + m0)];
            float2 v3 = sbuf[OIDX(n + m0 + m1)];
            acc += d0 * (v0.x * v0.x + v0.y * v0.y);
            acc += d1 * (v1.x * v1.x + v1.y * v1.y);
            acc += d2 * (v2.x * v2.x + v2.y * v2.y);
#define CROSS(vi, vj, aa, bb) { \
            float pr = vi.x * vj.x + vi.y * vj.y; \
            float pim = vi.x * vj.y - vi.y * vj.x; \
            acc += 2.f * (pr * (aa) - pim * (bb)); }
            CROSS(v1, v0, a10, b10)
            CROSS(v2, v0, a20, b20)
            CROSS(v2, v1, a21, b21)
            CROSS(v3, v0, a30, b30)
            CROSS(v3, v1, a31, b31)
            CROSS(v3, v2, a32, b32)
#undef CROSS
        }
#pragma unroll
        for (int off = 16; off; off >>= 1) acc += __shfl_xor_sync(FULLMASK, acc, off);
        if (lane == 0) part[w * 4 + warp] = acc;
    }
    __syncthreads();

    // head: out[b][j] = sum_w e[w] * head_w[j*7+w] + head_b[j]
    {
        int j = tid;
        float o = head_b[j];
#pragma unroll
        for (int w = 0; w < 7; ++w) {
            float e = part[w*4] + part[w*4+1] + part[w*4+2] + part[w*4+3];
            o = fmaf(e, head_w[j * 7 + w], o);
        }
        out[b * 128 + j] = o;
    }
}

// ---------------- launch ----------------
extern "C" void kernel_launch(void* const* d_in, const int* in_sizes, int n_in,
                              void* d_out, int out_size) {
    const float* z_t    = (const float*)d_in[0];
    const float* t      = (const float*)d_in[1];
    const float* te_w1  = (const float*)d_in[2];
    const float* te_b1  = (const float*)d_in[3];
    const float* te_w2  = (const float*)d_in[4];
    const float* te_b2  = (const float*)d_in[5];
    const float* ip_w1  = (const float*)d_in[6];
    const float* ip_b1  = (const float*)d_in[7];
    const float* ip_w2  = (const float*)d_in[8];
    const float* ip_b2  = (const float*)d_in[9];
    const float* prep   = (const float*)d_in[10];
    const float* sig    = (const float*)d_in[11];
    const float* qff    = (const float*)d_in[12];
    const float* A_obs  = (const float*)d_in[13];
    const float* B_obs  = (const float*)d_in[14];
    const float* D_obs  = (const float*)d_in[15];
    const float* head_w = (const float*)d_in[16];
    const float* head_b = (const float*)d_in[17];
    float* out = (float*)d_out;

    k_all<<<256, 128>>>(t, z_t, te_w1, te_b1, te_w2, te_b2, ip_w1, ip_b1, ip_w2, ip_b2,
                        prep, sig, qff, A_obs, B_obs, D_obs, head_w, head_b, out);
}